// round 1
// baseline (speedup 1.0000x reference)
#include <cuda_runtime.h>
#include <cstdint>
#include <math.h>

#define S_LEN 2048
#define Bsz   32
#define Hdim  512
#define K2    1024      // 2H
#define WSTRIDE 2048    // 4H (W row stride)

#define BM 128
#define BN 128
#define BK 32
#define SSTRIDE 40      // smem row stride in floats (padded)

// ---------------- scratch (device globals; no allocation allowed) ----------
__device__ float g_u_part[8 * Bsz * Hdim];          // K-split partials of u
__device__ float g_u[Bsz * Hdim];                   // u = W1*hidden + bias
__device__ float g_scores_part[4 * Bsz * S_LEN];    // per-N-tile score partials
__device__ float g_attn[Bsz * S_LEN];               // softmax weights
__device__ float g_ctx_part[16 * Bsz * K2];         // per-s-chunk context partials

__device__ __forceinline__ uint32_t f2tf32(float f) {
    uint32_t r;
    asm("cvt.rna.tf32.f32 %0, %1;" : "=r"(r) : "f"(f));
    return r;
}

// ---------------- phase 1: u_part[ks][b][h] = sum_{k in split} W1[h,k]*hidden[b,k]
// grid (4 h-tiles, 8 k-splits), 256 threads
__global__ void phase1_kernel(const float* __restrict__ hidden,
                              const float* __restrict__ W) {
    __shared__ float hid_s[Bsz][132];
    const int h0 = blockIdx.x * 128;
    const int k0 = blockIdx.y * 128;
    const int t  = threadIdx.x;

    // load hidden[:, k0:k0+128] -> smem (1024 float4)
    #pragma unroll
    for (int p = 0; p < 4; p++) {
        int lin = p * 256 + t;      // float4 index
        int b = lin >> 5;
        int kq = lin & 31;
        float4 v4 = *reinterpret_cast<const float4*>(hidden + (size_t)b * K2 + k0 + kq * 4);
        *reinterpret_cast<float4*>(&hid_s[b][kq * 4]) = v4;
    }
    __syncthreads();

    const int h  = h0 + (t >> 1);
    const int b0 = (t & 1) * 16;
    float acc[16];
    #pragma unroll
    for (int i = 0; i < 16; i++) acc[i] = 0.f;

    const float* wrow = W + (size_t)h * WSTRIDE + k0;
    for (int k = 0; k < 128; k += 4) {
        float4 w4 = *reinterpret_cast<const float4*>(wrow + k);
        #pragma unroll
        for (int bb = 0; bb < 16; bb++) {
            float4 h4 = *reinterpret_cast<const float4*>(&hid_s[b0 + bb][k]);
            acc[bb] += w4.x * h4.x + w4.y * h4.y + w4.z * h4.z + w4.w * h4.w;
        }
    }
    float* up = g_u_part + (size_t)blockIdx.y * (Bsz * Hdim);
    #pragma unroll
    for (int bb = 0; bb < 16; bb++) up[(size_t)(b0 + bb) * Hdim + h] = acc[bb];
}

// merge K-splits + bias -> g_u.  grid 64, 256 threads
__global__ void phase1b_kernel(const float* __restrict__ bias) {
    int idx = blockIdx.x * 256 + threadIdx.x;   // 0..16383
    float s = bias[idx & (Hdim - 1)];
    #pragma unroll
    for (int p = 0; p < 8; p++) s += g_u_part[p * (Bsz * Hdim) + idx];
    g_u[idx] = s;
}

// ---------------- phase 2: fused TF32 GEMM (enc @ W2^T) + tanh + v-dot ----
// grid (x = n_tile 0..3, y = m_tile 0..511), 256 threads (8 warps, 4x2)
__global__ void __launch_bounds__(256)
phase2_kernel(const float* __restrict__ enc,
              const float* __restrict__ W,
              const float* __restrict__ v) {
    __shared__ uint32_t As[BM * SSTRIDE];
    __shared__ uint32_t Bs[BN * SSTRIDE];
    __shared__ float u_s[BN], v_s[BN];
    __shared__ float rowsum2[2][BM];

    const int t    = threadIdx.x;
    const int lane = t & 31;
    const int warp = t >> 5;
    const int wm   = warp >> 1;   // 0..3 (M)
    const int wn   = warp & 1;    // 0..1 (N)
    const int m_tile = blockIdx.y;
    const int n_tile = blockIdx.x;
    const int m0 = m_tile * BM;
    const int n0 = n_tile * BN;
    const int b  = m0 >> 11;      // batch index (128-row tile never crosses b)

    if (t < BN) {
        u_s[t] = g_u[(size_t)b * Hdim + n0 + t];
        v_s[t] = v[n0 + t];
    }

    const int lr = t >> 3;        // 0..31 row within a load pass
    const int lq = t & 7;         // float4 col (k/4)
    const float* Abase = enc + (size_t)(m0 + lr) * K2 + lq * 4;
    const float* Bbase = W + (size_t)(n0 + lr) * WSTRIDE + K2 + lq * 4;

    float acc[2][8][4];
    #pragma unroll
    for (int i = 0; i < 2; i++)
        #pragma unroll
        for (int j = 0; j < 8; j++)
            #pragma unroll
            for (int c = 0; c < 4; c++) acc[i][j][c] = 0.f;

    float4 ra[4], rb[4];
    #pragma unroll
    for (int p = 0; p < 4; p++) {
        ra[p] = *reinterpret_cast<const float4*>(Abase + (size_t)p * 32 * K2);
        rb[p] = *reinterpret_cast<const float4*>(Bbase + (size_t)p * 32 * WSTRIDE);
    }

    for (int kc = 0; kc < K2; kc += BK) {
        __syncthreads();
        // store prefetched regs -> smem (cvt to tf32, xor-swizzled on k bit2)
        #pragma unroll
        for (int p = 0; p < 4; p++) {
            int r = lr + p * 32;
            int phys = (lq * 4) ^ (((r >> 2) & 1) << 2);
            uint4 sa, sb;
            sa.x = f2tf32(ra[p].x); sa.y = f2tf32(ra[p].y);
            sa.z = f2tf32(ra[p].z); sa.w = f2tf32(ra[p].w);
            sb.x = f2tf32(rb[p].x); sb.y = f2tf32(rb[p].y);
            sb.z = f2tf32(rb[p].z); sb.w = f2tf32(rb[p].w);
            *reinterpret_cast<uint4*>(&As[r * SSTRIDE + phys]) = sa;
            *reinterpret_cast<uint4*>(&Bs[r * SSTRIDE + phys]) = sb;
        }
        __syncthreads();
        // prefetch next chunk (overlaps with compute below)
        if (kc + BK < K2) {
            #pragma unroll
            for (int p = 0; p < 4; p++) {
                ra[p] = *reinterpret_cast<const float4*>(Abase + (size_t)p * 32 * K2 + kc + BK);
                rb[p] = *reinterpret_cast<const float4*>(Bbase + (size_t)p * 32 * WSTRIDE + kc + BK);
            }
        }
        // compute: 4 k-steps of 8, warp tile 32x64, mma m16n8k8 tf32
        #pragma unroll
        for (int ks = 0; ks < 4; ks++) {
            const int kk = ks * 8;
            uint32_t af[2][4];
            #pragma unroll
            for (int mt = 0; mt < 2; mt++) {
                int r0 = wm * 32 + mt * 16 + (lane >> 2);
                int r1 = r0 + 8;
                int c0 = kk + (lane & 3);
                int c1 = c0 + 4;
                int s0 = ((r0 >> 2) & 1) << 2;
                int s1 = ((r1 >> 2) & 1) << 2;
                af[mt][0] = As[r0 * SSTRIDE + (c0 ^ s0)];
                af[mt][1] = As[r1 * SSTRIDE + (c0 ^ s1)];
                af[mt][2] = As[r0 * SSTRIDE + (c1 ^ s0)];
                af[mt][3] = As[r1 * SSTRIDE + (c1 ^ s1)];
            }
            #pragma unroll
            for (int nt = 0; nt < 8; nt++) {
                int n  = wn * 64 + nt * 8 + (lane >> 2);
                int c0 = kk + (lane & 3);
                int sn = ((n >> 2) & 1) << 2;
                uint32_t b0r = Bs[n * SSTRIDE + (c0 ^ sn)];
                uint32_t b1r = Bs[n * SSTRIDE + ((c0 + 4) ^ sn)];
                #pragma unroll
                for (int mt = 0; mt < 2; mt++) {
                    asm volatile(
                        "mma.sync.aligned.m16n8k8.row.col.f32.tf32.tf32.f32 "
                        "{%0,%1,%2,%3}, {%4,%5,%6,%7}, {%8,%9}, {%0,%1,%2,%3};\n"
                        : "+f"(acc[mt][nt][0]), "+f"(acc[mt][nt][1]),
                          "+f"(acc[mt][nt][2]), "+f"(acc[mt][nt][3])
                        : "r"(af[mt][0]), "r"(af[mt][1]), "r"(af[mt][2]), "r"(af[mt][3]),
                          "r"(b0r), "r"(b1r));
                }
            }
        }
    }

    // epilogue: tanh(acc + u) * v, reduce over the 128 local h's per row
    __syncthreads();
    const int q  = lane >> 2;
    const int t4 = lane & 3;
    #pragma unroll
    for (int mt = 0; mt < 2; mt++) {
        float p0 = 0.f, p1 = 0.f;   // rows r, r+8
        #pragma unroll
        for (int nt = 0; nt < 8; nt++) {
            int col = wn * 64 + nt * 8 + 2 * t4;
            float uu0 = u_s[col],     uu1 = u_s[col + 1];
            float vv0 = v_s[col],     vv1 = v_s[col + 1];
            p0 += tanhf(acc[mt][nt][0] + uu0) * vv0 + tanhf(acc[mt][nt][1] + uu1) * vv1;
            p1 += tanhf(acc[mt][nt][2] + uu0) * vv0 + tanhf(acc[mt][nt][3] + uu1) * vv1;
        }
        p0 += __shfl_xor_sync(0xffffffffu, p0, 1);
        p0 += __shfl_xor_sync(0xffffffffu, p0, 2);
        p1 += __shfl_xor_sync(0xffffffffu, p1, 1);
        p1 += __shfl_xor_sync(0xffffffffu, p1, 2);
        if (t4 == 0) {
            int r = wm * 32 + mt * 16 + q;
            rowsum2[wn][r]     = p0;   // unique writer per (wn, r)
            rowsum2[wn][r + 8] = p1;
        }
    }
    __syncthreads();
    if (t < BM)
        g_scores_part[(size_t)n_tile * (Bsz * S_LEN) + m0 + t] =
            rowsum2[0][t] + rowsum2[1][t];
}

// ---------------- phase 3: softmax over S per batch row. grid 32, 256 thr --
__global__ void softmax_kernel() {
    __shared__ float red[256];
    const int b = blockIdx.x, t = threadIdx.x;
    const int base = b * S_LEN;

    float mx = -1e30f;
    for (int s = t; s < S_LEN; s += 256) {
        float val = g_scores_part[0 * (Bsz * S_LEN) + base + s]
                  + g_scores_part[1 * (Bsz * S_LEN) + base + s]
                  + g_scores_part[2 * (Bsz * S_LEN) + base + s]
                  + g_scores_part[3 * (Bsz * S_LEN) + base + s];
        g_attn[base + s] = val;
        mx = fmaxf(mx, val);
    }
    red[t] = mx; __syncthreads();
    for (int o = 128; o > 0; o >>= 1) {
        if (t < o) red[t] = fmaxf(red[t], red[t + o]);
        __syncthreads();
    }
    mx = red[0]; __syncthreads();

    float sum = 0.f;
    for (int s = t; s < S_LEN; s += 256) {
        float e = __expf(g_attn[base + s] - mx);
        g_attn[base + s] = e;
        sum += e;
    }
    red[t] = sum; __syncthreads();
    for (int o = 128; o > 0; o >>= 1) {
        if (t < o) red[t] += red[t + o];
        __syncthreads();
    }
    float inv = 1.f / red[0];
    for (int s = t; s < S_LEN; s += 256) g_attn[base + s] *= inv;
}

// ---------------- phase 4: context partials. grid (16 chunks, 32 b), 256 thr
__global__ void context_kernel(const float* __restrict__ enc) {
    __shared__ float a_s[128];
    const int chunk = blockIdx.x, b = blockIdx.y, t = threadIdx.x;
    const int s0 = chunk * 128;
    if (t < 128) a_s[t] = g_attn[b * S_LEN + s0 + t];
    __syncthreads();

    float4 acc = {0.f, 0.f, 0.f, 0.f};
    const float4* ep = reinterpret_cast<const float4*>(
        enc + ((size_t)(b * S_LEN + s0)) * K2) + t;
    #pragma unroll 4
    for (int ss = 0; ss < 128; ss++) {
        float a = a_s[ss];
        float4 e = ep[(size_t)ss * (K2 / 4)];
        acc.x += a * e.x; acc.y += a * e.y; acc.z += a * e.z; acc.w += a * e.w;
    }
    reinterpret_cast<float4*>(g_ctx_part + ((size_t)(chunk * Bsz + b)) * K2)[t] = acc;
}

// reduce 16 chunk-partials -> d_out.  grid 32, 256 thr
__global__ void context_reduce_kernel(float* __restrict__ out) {
    const int b = blockIdx.x, t = threadIdx.x;
    float4 s = {0.f, 0.f, 0.f, 0.f};
    #pragma unroll
    for (int c = 0; c < 16; c++) {
        float4 p = reinterpret_cast<const float4*>(
            g_ctx_part + ((size_t)(c * Bsz + b)) * K2)[t];
        s.x += p.x; s.y += p.y; s.z += p.z; s.w += p.w;
    }
    reinterpret_cast<float4*>(out + (size_t)b * K2)[t] = s;
}

// ---------------- launch ----------------------------------------------------
extern "C" void kernel_launch(void* const* d_in, const int* in_sizes, int n_in,
                              void* d_out, int out_size) {
    const float* hidden = (const float*)d_in[0];   // [32, 1024]
    const float* enc    = (const float*)d_in[1];   // [32, 2048, 1024]
    const float* W      = (const float*)d_in[2];   // [512, 2048]
    const float* bias   = (const float*)d_in[3];   // [512]
    const float* v      = (const float*)d_in[4];   // [512]
    float* out = (float*)d_out;                    // [32, 1024]

    phase1_kernel<<<dim3(4, 8), 256>>>(hidden, W);
    phase1b_kernel<<<64, 256>>>(bias);
    phase2_kernel<<<dim3(4, 512), 256>>>(enc, W, v);
    softmax_kernel<<<32, 256>>>();
    context_kernel<<<dim3(16, 32), 256>>>(enc);
    context_reduce_kernel<<<32, 256>>>(out);
}

// round 3
// speedup vs baseline: 2.9881x; 2.9881x over previous
#include <cuda_runtime.h>
#include <cuda.h>
#include <cstdint>
#include <math.h>

#define S_LEN 2048
#define Bsz   32
#define Hdim  512
#define K2    1024      // 2H
#define WSTRIDE 2048    // 4H (W row stride)

#define NCHUNK 32       // K2 / 32
#define A_TILE 16384    // 128 rows * 128B
#define B_TILE 32768    // 256 rows * 128B
#define STAGE_BYTES (A_TILE + B_TILE)   // 49152
#define DSMEM_BYTES (2 * STAGE_BYTES + 1024)

// arch-feature gate: tcgen05 only exists in the sm_103a pass
#if defined(__CUDA_ARCH__) && defined(__CUDA_ARCH_FEAT_SM103_ALL)
#define TCGEN_OK 1
#else
#define TCGEN_OK 0
#endif

// idesc: dtype=f32(1)<<4, atype=tf32(2)<<7, btype=tf32(2)<<10, N/8=32<<17, M/16=8<<24
#define IDESC_TF32 ((1u<<4) | (2u<<7) | (2u<<10) | (32u<<17) | (8u<<24))

// ---------------- scratch (device globals; no allocation allowed) ----------
__device__ float g_u_part[8 * Bsz * Hdim];
__device__ float g_u[Bsz * Hdim];
__device__ float g_scores_part[2 * Bsz * S_LEN];   // [n_half][b*S+s]
__device__ float g_attn[Bsz * S_LEN];
__device__ float g_ctx_part[16 * Bsz * K2];

// ---------------- PTX helpers (sm_90-safe subset) ---------------------------
__device__ __forceinline__ uint32_t smem_u32(const void* p) {
    uint32_t a;
    asm("{ .reg .u64 t; cvta.to.shared.u64 t, %1; cvt.u32.u64 %0, t; }" : "=r"(a) : "l"(p));
    return a;
}

#define MBAR_INIT(addr, cnt) \
    asm volatile("mbarrier.init.shared.b64 [%0], %1;" :: "r"(addr), "r"(cnt) : "memory")
#define MBAR_EXPECT_TX(addr, bytes) \
    asm volatile("mbarrier.arrive.expect_tx.shared.b64 _, [%0], %1;" :: "r"(addr), "r"(bytes) : "memory")
#define MBAR_ARRIVE(addr) \
    asm volatile("mbarrier.arrive.shared.b64 _, [%0];" :: "r"(addr) : "memory")

#define MBAR_WAIT(addr, parity) do { \
    asm volatile( \
        "{\n\t.reg .pred P1;\n\t" \
        "WL_%=:\n\t" \
        "mbarrier.try_wait.parity.acquire.cta.shared::cta.b64 P1, [%0], %1, 0x989680;\n\t" \
        "@P1 bra.uni WD_%=;\n\t" \
        "bra.uni WL_%=;\n\t" \
        "WD_%=:\n\t}" \
        :: "r"(addr), "r"(parity) : "memory"); \
} while (0)

#define TMA_LOAD_2D(dst, tmap, x, y, mbar) \
    asm volatile( \
        "cp.async.bulk.tensor.2d.shared::cta.global.tile.mbarrier::complete_tx::bytes " \
        "[%0], [%1, {%2, %3}], [%4];" \
        :: "r"(dst), "l"(tmap), "r"(x), "r"(y), "r"(mbar) : "memory")

#if TCGEN_OK
#define TCGEN05_ALLOC(slot, ncols) \
    asm volatile("tcgen05.alloc.cta_group::1.sync.aligned.shared::cta.b32 [%0], %1;" \
        :: "r"(slot), "r"(ncols) : "memory")
#define TCGEN05_RELINQ() \
    asm volatile("tcgen05.relinquish_alloc_permit.cta_group::1.sync.aligned;")
#define TCGEN05_DEALLOC(base, ncols) \
    asm volatile("tcgen05.dealloc.cta_group::1.sync.aligned.b32 %0, %1;" :: "r"(base), "r"(ncols))
#define TCGEN05_COMMIT(mbar) \
    asm volatile("tcgen05.commit.cta_group::1.mbarrier::arrive::one.shared::cluster.b64 [%0];" \
        :: "r"(mbar) : "memory")
#define TCGEN05_FENCE_AFTER() \
    asm volatile("tcgen05.fence::after_thread_sync;" ::: "memory")
#define TCGEN05_WAIT_LD() \
    asm volatile("tcgen05.wait::ld.sync.aligned;" ::: "memory")

__device__ __forceinline__ void mma_tf32(uint32_t d_tmem, uint64_t adesc, uint64_t bdesc,
                                         uint32_t idesc, uint32_t enable) {
    uint32_t zero = 0;
    asm volatile(
        "{\n\t.reg .pred p;\n\t"
        "setp.ne.u32 p, %6, 0;\n\t"
        "tcgen05.mma.cta_group::1.kind::tf32 [%0], %1, %2, %3, {%4, %4, %4, %4}, p;\n\t}"
        :: "r"(d_tmem), "l"(adesc), "l"(bdesc), "r"(idesc), "r"(zero), "r"(zero), "r"(enable)
        : "memory");
}

// SW128, Blackwell v1, SBO=64, LBO=1 (K-major, 128B rows)
__device__ __forceinline__ uint64_t make_desc(uint32_t addr) {
    const uint64_t base =
        (uint64_t(2) << 61) | (uint64_t(1) << 46) | (uint64_t(64) << 32) | (uint64_t(1) << 16);
    return base | ((uint64_t)(addr >> 4) & 0x3FFF);
}

#define LDTM_X32(r, addr) \
    asm volatile( \
        "tcgen05.ld.sync.aligned.32x32b.x32.b32 " \
        "{%0,%1,%2,%3,%4,%5,%6,%7,%8,%9,%10,%11,%12,%13,%14,%15," \
        "%16,%17,%18,%19,%20,%21,%22,%23,%24,%25,%26,%27,%28,%29,%30,%31}, [%32];" \
        : "=r"((r)[0]),"=r"((r)[1]),"=r"((r)[2]),"=r"((r)[3]), \
          "=r"((r)[4]),"=r"((r)[5]),"=r"((r)[6]),"=r"((r)[7]), \
          "=r"((r)[8]),"=r"((r)[9]),"=r"((r)[10]),"=r"((r)[11]), \
          "=r"((r)[12]),"=r"((r)[13]),"=r"((r)[14]),"=r"((r)[15]), \
          "=r"((r)[16]),"=r"((r)[17]),"=r"((r)[18]),"=r"((r)[19]), \
          "=r"((r)[20]),"=r"((r)[21]),"=r"((r)[22]),"=r"((r)[23]), \
          "=r"((r)[24]),"=r"((r)[25]),"=r"((r)[26]),"=r"((r)[27]), \
          "=r"((r)[28]),"=r"((r)[29]),"=r"((r)[30]),"=r"((r)[31]) \
        : "r"(addr))
#endif // TCGEN_OK

// swizzled SW128 scalar load: element (row r, k-col k) of a 128B-row tile
__device__ __forceinline__ float lds_sw(const char* base, int r, int k) {
    return *reinterpret_cast<const float*>(base + r * 128 + ((k * 4) ^ ((r & 7) << 4)));
}

// ---------------- phase 1: u = W1 * hidden (K-split) -----------------------
__global__ void phase1_kernel(const float* __restrict__ hidden,
                              const float* __restrict__ W) {
    __shared__ float hid_s[Bsz][132];
    const int h0 = blockIdx.x * 128;
    const int k0 = blockIdx.y * 128;
    const int t  = threadIdx.x;

    #pragma unroll
    for (int p = 0; p < 4; p++) {
        int lin = p * 256 + t;
        int b = lin >> 5;
        int kq = lin & 31;
        float4 v4 = *reinterpret_cast<const float4*>(hidden + (size_t)b * K2 + k0 + kq * 4);
        *reinterpret_cast<float4*>(&hid_s[b][kq * 4]) = v4;
    }
    __syncthreads();

    const int h  = h0 + (t >> 1);
    const int b0 = (t & 1) * 16;
    float acc[16];
    #pragma unroll
    for (int i = 0; i < 16; i++) acc[i] = 0.f;

    const float* wrow = W + (size_t)h * WSTRIDE + k0;
    for (int k = 0; k < 128; k += 4) {
        float4 w4 = *reinterpret_cast<const float4*>(wrow + k);
        #pragma unroll
        for (int bb = 0; bb < 16; bb++) {
            float4 h4 = *reinterpret_cast<const float4*>(&hid_s[b0 + bb][k]);
            acc[bb] += w4.x * h4.x + w4.y * h4.y + w4.z * h4.z + w4.w * h4.w;
        }
    }
    float* up = g_u_part + (size_t)blockIdx.y * (Bsz * Hdim);
    #pragma unroll
    for (int bb = 0; bb < 16; bb++) up[(size_t)(b0 + bb) * Hdim + h] = acc[bb];
}

__global__ void phase1b_kernel(const float* __restrict__ bias) {
    int idx = blockIdx.x * 256 + threadIdx.x;
    float s = bias[idx & (Hdim - 1)];
    #pragma unroll
    for (int p = 0; p < 8; p++) s += g_u_part[p * (Bsz * Hdim) + idx];
    g_u[idx] = s;
}

// ---------------- phase 2: fused GEMM (enc @ W2^T) + tanh + v-dot ----------
// grid (2, 512): x = n-half (256 cols), y = 128-row tile. 256 threads.
__global__ void __launch_bounds__(256)
phase2_kernel(const __grid_constant__ CUtensorMap tma_a,
              const __grid_constant__ CUtensorMap tma_b,
              const float* __restrict__ v) {
    extern __shared__ char dyn[];
    __shared__ __align__(16) uint64_t mbar_full[2];
    __shared__ __align__(16) uint64_t mbar_done[2];
    __shared__ __align__(16) uint64_t mbar_final;
    __shared__ uint32_t tmem_slot;
    __shared__ float u_s[256], v_s[256];
    __shared__ float sp2[2][128];

    const int t    = threadIdx.x;
    const int wid  = t >> 5;
    const int lane = t & 31;
    const int n0   = blockIdx.x * 256;
    const int m0   = blockIdx.y * 128;    // global row (b*2048 + s0)
    const int b    = m0 >> 11;

    uint32_t dbase = smem_u32(dyn);
    dbase = (dbase + 1023u) & ~1023u;
    char* dynA = (char*)dyn + (dbase - smem_u32(dyn));

    u_s[t & 255] = g_u[(size_t)b * Hdim + n0 + (t & 255)];
    v_s[t & 255] = v[n0 + (t & 255)];

    const uint32_t mf0 = smem_u32(&mbar_full[0]);
    const uint32_t mf1 = smem_u32(&mbar_full[1]);
    const uint32_t md0 = smem_u32(&mbar_done[0]);
    const uint32_t md1 = smem_u32(&mbar_done[1]);
    const uint32_t mfin = smem_u32(&mbar_final);

#if TCGEN_OK
    // ============================ tcgen05 path ==============================
    if (wid == 0) {
        TCGEN05_ALLOC(smem_u32(&tmem_slot), 256);
        TCGEN05_RELINQ();
    }
    if (t == 0) {
        MBAR_INIT(mf0, 1); MBAR_INIT(mf1, 1);
        MBAR_INIT(md0, 1); MBAR_INIT(md1, 1);
        MBAR_INIT(mfin, 1);
    }
    __syncthreads();
    const uint32_t tmem = tmem_slot;

    if (t == 0) {
        #pragma unroll
        for (int i = 0; i < 2; i++) {
            uint32_t mb = i ? mf1 : mf0;
            uint32_t base = dbase + (uint32_t)i * STAGE_BYTES;
            MBAR_EXPECT_TX(mb, STAGE_BYTES);
            TMA_LOAD_2D(base,          &tma_a, i * 32,      m0, mb);
            TMA_LOAD_2D(base + A_TILE, &tma_b, K2 + i * 32, n0, mb);
        }
        for (int i = 0; i < NCHUNK; i++) {
            const int buf = i & 1;
            const uint32_t ph = (uint32_t)((i >> 1) & 1);
            const uint32_t mf = buf ? mf1 : mf0;
            const uint32_t md = buf ? md1 : md0;
            MBAR_WAIT(mf, ph);
            const uint32_t base = dbase + (uint32_t)buf * STAGE_BYTES;
            const uint64_t adesc = make_desc(base);
            const uint64_t bdesc = make_desc(base + A_TILE);
            #pragma unroll
            for (int ks = 0; ks < 4; ks++) {
                mma_tf32(tmem, adesc + ks * 2, bdesc + ks * 2,
                         IDESC_TF32, (i > 0 || ks > 0) ? 1u : 0u);
            }
            TCGEN05_COMMIT(md);
            if (i + 2 < NCHUNK) {
                MBAR_WAIT(md, ph);
                const int j = i + 2;
                const uint32_t nb = dbase + (uint32_t)buf * STAGE_BYTES;
                MBAR_EXPECT_TX(mf, STAGE_BYTES);
                TMA_LOAD_2D(nb,          &tma_a, j * 32,      m0, mf);
                TMA_LOAD_2D(nb + A_TILE, &tma_b, K2 + j * 32, n0, mf);
            }
        }
        TCGEN05_COMMIT(mfin);
    }

    MBAR_WAIT(mfin, 0);
    TCGEN05_FENCE_AFTER();

    {   // epilogue: warps 0-3 cols [0,128), warps 4-7 cols [128,256)
        const int half = wid >> 2;
        const int colbase = half * 128;
        const int row = (wid & 3) * 32 + lane;
        float acc = 0.f;
        #pragma unroll
        for (int c = 0; c < 4; c++) {
            uint32_t r[32];
            LDTM_X32(r, tmem + colbase + c * 32);
            TCGEN05_WAIT_LD();
            #pragma unroll
            for (int j = 0; j < 32; j++) {
                const int col = colbase + c * 32 + j;
                acc += tanhf(__uint_as_float(r[j]) + u_s[col]) * v_s[col];
            }
        }
        sp2[half][row] = acc;
    }
    __syncthreads();
    if (t < 128)
        g_scores_part[(size_t)blockIdx.x * (Bsz * S_LEN) + m0 + t] =
            sp2[0][t] + sp2[1][t];
    __syncthreads();
    if (wid == 0) TCGEN05_DEALLOC(tmem, 256);

#else
    // ========================= mma.sync fallback ============================
    (void)tmem_slot; (void)mfin;
    if (t == 0) {
        MBAR_INIT(mf0, 1);   MBAR_INIT(mf1, 1);
        MBAR_INIT(md0, 256); MBAR_INIT(md1, 256);
    }
    __syncthreads();

    if (t == 0) {
        #pragma unroll
        for (int i = 0; i < 2; i++) {
            uint32_t mb = i ? mf1 : mf0;
            uint32_t base = dbase + (uint32_t)i * STAGE_BYTES;
            MBAR_EXPECT_TX(mb, STAGE_BYTES);
            TMA_LOAD_2D(base,          &tma_a, i * 32,      m0, mb);
            TMA_LOAD_2D(base + A_TILE, &tma_b, K2 + i * 32, n0, mb);
        }
    }

    const int wm = wid >> 1;      // 0..3 (32-row slice)
    const int wn = wid & 1;       // 0..1 (128-col slice)
    float acc[2][16][4];
    #pragma unroll
    for (int i = 0; i < 2; i++)
        #pragma unroll
        for (int j = 0; j < 16; j++)
            #pragma unroll
            for (int c = 0; c < 4; c++) acc[i][j][c] = 0.f;

    for (int i = 0; i < NCHUNK; i++) {
        const int buf = i & 1;
        const uint32_t ph = (uint32_t)((i >> 1) & 1);
        const uint32_t mf = buf ? mf1 : mf0;
        const uint32_t md = buf ? md1 : md0;
        MBAR_WAIT(mf, ph);
        const char* As = dynA + buf * STAGE_BYTES;
        const char* Bs = As + A_TILE;
        #pragma unroll
        for (int ks = 0; ks < 4; ks++) {
            const int k0 = ks * 8 + (lane & 3);
            const int k1 = k0 + 4;
            uint32_t af[2][4];
            #pragma unroll
            for (int mt = 0; mt < 2; mt++) {
                int r0 = wm * 32 + mt * 16 + (lane >> 2);
                int r1 = r0 + 8;
                af[mt][0] = __float_as_uint(lds_sw(As, r0, k0));
                af[mt][1] = __float_as_uint(lds_sw(As, r1, k0));
                af[mt][2] = __float_as_uint(lds_sw(As, r0, k1));
                af[mt][3] = __float_as_uint(lds_sw(As, r1, k1));
            }
            #pragma unroll
            for (int nt = 0; nt < 16; nt++) {
                int n = wn * 128 + nt * 8 + (lane >> 2);
                uint32_t b0r = __float_as_uint(lds_sw(Bs, n, k0));
                uint32_t b1r = __float_as_uint(lds_sw(Bs, n, k1));
                #pragma unroll
                for (int mt = 0; mt < 2; mt++) {
                    asm volatile(
                        "mma.sync.aligned.m16n8k8.row.col.f32.tf32.tf32.f32 "
                        "{%0,%1,%2,%3}, {%4,%5,%6,%7}, {%8,%9}, {%0,%1,%2,%3};\n"
                        : "+f"(acc[mt][nt][0]), "+f"(acc[mt][nt][1]),
                          "+f"(acc[mt][nt][2]), "+f"(acc[mt][nt][3])
                        : "r"(af[mt][0]), "r"(af[mt][1]), "r"(af[mt][2]), "r"(af[mt][3]),
                          "r"(b0r), "r"(b1r));
                }
            }
        }
        MBAR_ARRIVE(md);
        if (t == 0 && i + 2 < NCHUNK) {
            MBAR_WAIT(md, ph);
            const int j = i + 2;
            const uint32_t nb = dbase + (uint32_t)buf * STAGE_BYTES;
            MBAR_EXPECT_TX(mf, STAGE_BYTES);
            TMA_LOAD_2D(nb,          &tma_a, j * 32,      m0, mf);
            TMA_LOAD_2D(nb + A_TILE, &tma_b, K2 + j * 32, n0, mf);
        }
    }

    {   // epilogue: tanh(acc + u) * v, reduce 128 local cols per row
        const int q  = lane >> 2;
        const int t4 = lane & 3;
        #pragma unroll
        for (int mt = 0; mt < 2; mt++) {
            float p0 = 0.f, p1 = 0.f;
            #pragma unroll
            for (int nt = 0; nt < 16; nt++) {
                int col = wn * 128 + nt * 8 + 2 * t4;
                float uu0 = u_s[col],     uu1 = u_s[col + 1];
                float vv0 = v_s[col],     vv1 = v_s[col + 1];
                p0 += tanhf(acc[mt][nt][0] + uu0) * vv0 + tanhf(acc[mt][nt][1] + uu1) * vv1;
                p1 += tanhf(acc[mt][nt][2] + uu0) * vv0 + tanhf(acc[mt][nt][3] + uu1) * vv1;
            }
            p0 += __shfl_xor_sync(0xffffffffu, p0, 1);
            p0 += __shfl_xor_sync(0xffffffffu, p0, 2);
            p1 += __shfl_xor_sync(0xffffffffu, p1, 1);
            p1 += __shfl_xor_sync(0xffffffffu, p1, 2);
            if (t4 == 0) {
                int r = wm * 32 + mt * 16 + q;
                sp2[wn][r]     = p0;
                sp2[wn][r + 8] = p1;
            }
        }
    }
    __syncthreads();
    if (t < 128)
        g_scores_part[(size_t)blockIdx.x * (Bsz * S_LEN) + m0 + t] =
            sp2[0][t] + sp2[1][t];
#endif
}

// ---------------- phase 3: softmax over S per batch. grid 32, 256 thr ------
__global__ void softmax_kernel() {
    __shared__ float red[256];
    const int b = blockIdx.x, t = threadIdx.x;
    const int base = b * S_LEN;

    float mx = -1e30f;
    for (int s = t; s < S_LEN; s += 256) {
        float val = g_scores_part[base + s] + g_scores_part[Bsz * S_LEN + base + s];
        g_attn[base + s] = val;
        mx = fmaxf(mx, val);
    }
    red[t] = mx; __syncthreads();
    for (int o = 128; o > 0; o >>= 1) {
        if (t < o) red[t] = fmaxf(red[t], red[t + o]);
        __syncthreads();
    }
    mx = red[0]; __syncthreads();

    float sum = 0.f;
    for (int s = t; s < S_LEN; s += 256) {
        float e = __expf(g_attn[base + s] - mx);
        g_attn[base + s] = e;
        sum += e;
    }
    red[t] = sum; __syncthreads();
    for (int o = 128; o > 0; o >>= 1) {
        if (t < o) red[t] += red[t + o];
        __syncthreads();
    }
    float inv = 1.f / red[0];
    for (int s = t; s < S_LEN; s += 256) g_attn[base + s] *= inv;
}

// ---------------- phase 4: context partials. grid (16, 32), 256 thr --------
__global__ void context_kernel(const float* __restrict__ enc) {
    __shared__ float a_s[128];
    const int chunk = blockIdx.x, b = blockIdx.y, t = threadIdx.x;
    const int s0 = chunk * 128;
    if (t < 128) a_s[t] = g_attn[b * S_LEN + s0 + t];
    __syncthreads();

    float4 acc = {0.f, 0.f, 0.f, 0.f};
    const float4* ep = reinterpret_cast<const float4*>(
        enc + ((size_t)(b * S_LEN + s0)) * K2) + t;
    #pragma unroll 4
    for (int ss = 0; ss < 128; ss++) {
        float a = a_s[ss];
        float4 e = ep[(size_t)ss * (K2 / 4)];
        acc.x += a * e.x; acc.y += a * e.y; acc.z += a * e.z; acc.w += a * e.w;
    }
    reinterpret_cast<float4*>(g_ctx_part + ((size_t)(chunk * Bsz + b)) * K2)[t] = acc;
}

__global__ void context_reduce_kernel(float* __restrict__ out) {
    const int b = blockIdx.x, t = threadIdx.x;
    float4 s = {0.f, 0.f, 0.f, 0.f};
    #pragma unroll
    for (int c = 0; c < 16; c++) {
        float4 p = reinterpret_cast<const float4*>(
            g_ctx_part + ((size_t)(c * Bsz + b)) * K2)[t];
        s.x += p.x; s.y += p.y; s.z += p.z; s.w += p.w;
    }
    reinterpret_cast<float4*>(out + (size_t)b * K2)[t] = s;
}

// ---------------- host: tensormap build + launch ----------------------------
typedef CUresult (*PFN_encodeTiled)(
    CUtensorMap*, CUtensorMapDataType, cuuint32_t, void*,
    const cuuint64_t*, const cuuint64_t*, const cuuint32_t*, const cuuint32_t*,
    CUtensorMapInterleave, CUtensorMapSwizzle, CUtensorMapL2promotion,
    CUtensorMapFloatOOBfill);

extern "C" void kernel_launch(void* const* d_in, const int* in_sizes, int n_in,
                              void* d_out, int out_size) {
    const float* hidden = (const float*)d_in[0];   // [32, 1024]
    const float* enc    = (const float*)d_in[1];   // [32, 2048, 1024]
    const float* W      = (const float*)d_in[2];   // [512, 2048]
    const float* bias   = (const float*)d_in[3];   // [512]
    const float* v      = (const float*)d_in[4];   // [512]
    float* out = (float*)d_out;                    // [32, 1024]

    void* fn = nullptr;
    cudaDriverEntryPointQueryResult qr;
    cudaGetDriverEntryPoint("cuTensorMapEncodeTiled", &fn, cudaEnableDefault, &qr);
    PFN_encodeTiled encode = (PFN_encodeTiled)fn;

    CUtensorMap tma_a, tma_b;
    {
        // enc as 2D [1024 cols, 65536 rows], box [32, 128], SW128
        cuuint64_t dims[2]    = {(cuuint64_t)K2, (cuuint64_t)(Bsz * S_LEN)};
        cuuint64_t strides[1] = {(cuuint64_t)K2 * sizeof(float)};
        cuuint32_t box[2]     = {32, 128};
        cuuint32_t estr[2]    = {1, 1};
        encode(&tma_a, CU_TENSOR_MAP_DATA_TYPE_FLOAT32, 2, (void*)enc,
               dims, strides, box, estr,
               CU_TENSOR_MAP_INTERLEAVE_NONE, CU_TENSOR_MAP_SWIZZLE_128B,
               CU_TENSOR_MAP_L2_PROMOTION_L2_128B, CU_TENSOR_MAP_FLOAT_OOB_FILL_NONE);
    }
    {
        // W as 2D [2048 cols, 512 rows], box [32, 256], SW128
        cuuint64_t dims[2]    = {(cuuint64_t)WSTRIDE, (cuuint64_t)Hdim};
        cuuint64_t strides[1] = {(cuuint64_t)WSTRIDE * sizeof(float)};
        cuuint32_t box[2]     = {32, 256};
        cuuint32_t estr[2]    = {1, 1};
        encode(&tma_b, CU_TENSOR_MAP_DATA_TYPE_FLOAT32, 2, (void*)W,
               dims, strides, box, estr,
               CU_TENSOR_MAP_INTERLEAVE_NONE, CU_TENSOR_MAP_SWIZZLE_128B,
               CU_TENSOR_MAP_L2_PROMOTION_L2_128B, CU_TENSOR_MAP_FLOAT_OOB_FILL_NONE);
    }

    cudaFuncSetAttribute(phase2_kernel, cudaFuncAttributeMaxDynamicSharedMemorySize,
                         DSMEM_BYTES);

    phase1_kernel<<<dim3(4, 8), 256>>>(hidden, W);
    phase1b_kernel<<<64, 256>>>(bias);
    phase2_kernel<<<dim3(2, 512), 256, DSMEM_BYTES>>>(tma_a, tma_b, v);
    softmax_kernel<<<32, 256>>>();
    context_kernel<<<dim3(16, 32), 256>>>(enc);
    context_reduce_kernel<<<32, 256>>>(out);
}